// round 3
// baseline (speedup 1.0000x reference)
#include <cuda_runtime.h>
#include <cstdint>

#define BATCH   64
#define QN      1000
#define CN      1203
#define NTOT    (QN * CN)        // 1203000 per batch
#define N4      (NTOT / 4)       // 300750 float4 per batch
#define KTOP    100
#define KEEP    192              // survivors per chunk (generous)
#define CHUNKS  16
#define T1      512              // threads, chunk kernel
#define BUF     4096             // shared candidate buffer (u64)
#define T2      1024             // threads, merge kernel
#define MERGE_N 4096             // next pow2 >= CHUNKS*KEEP = 3072

// per-chunk candidates: packed (prob_bits<<32)|~idx  (single total order everywhere)
__device__ unsigned long long g_cand[BATCH * CHUNKS * KEEP];

// Reference sigmoid hypothesis: XLA-GPU logistic -> 0.5 + 0.5*tanh.approx(0.5*x).
// 0.5*x and 0.5*t are exact; single rounding in the fma -> deterministic bits.
__device__ __forceinline__ float ref_sigmoid(float x) {
    float t;
    asm("tanh.approx.f32 %0, %1;" : "=f"(t) : "f"(x * 0.5f));
    return fmaf(0.5f, t, 0.5f);
}

__device__ __forceinline__ unsigned long long pack(float prob, int idx) {
    // prob in [0,1): positive f32 -> raw bits are order-preserving.
    return ((unsigned long long)__float_as_uint(prob) << 32)
         | (unsigned int)(~idx);   // smaller idx wins ties
}

template <int NSORT, int NTHREADS>
__device__ __forceinline__ void bitonic_desc(unsigned long long* s, int tid) {
    #pragma unroll 1
    for (int k = 2; k <= NSORT; k <<= 1) {
        #pragma unroll 1
        for (int j = k >> 1; j > 0; j >>= 1) {
            #pragma unroll
            for (int i = tid; i < NSORT; i += NTHREADS) {
                int ixj = i ^ j;
                if (ixj > i) {
                    unsigned long long a = s[i], b = s[ixj];
                    if ((a < b) == ((i & k) == 0)) { s[i] = b; s[ixj] = a; }
                }
            }
            __syncthreads();
        }
    }
}

// ---------------------------------------------------------------------------
// Kernel 1: per (batch, chunk) streaming top-KEEP by (mufu_prob, ~idx) u64 key
// ---------------------------------------------------------------------------
__global__ __launch_bounds__(T1, 2)
void topk_chunk_kernel(const float* __restrict__ logits) {
    __shared__ unsigned long long buf[BUF];
    __shared__ int cnt;
    __shared__ unsigned long long thr64;   // full-key threshold (KEEP-th best so far)
    __shared__ float guard;                // conservative logit guard for fast path

    const int b   = blockIdx.y;
    const int ch  = blockIdx.x;
    const int tid = threadIdx.x;

    const float4* __restrict__ base =
        reinterpret_cast<const float4*>(logits + (size_t)b * NTOT);

    const int per = (N4 + CHUNKS - 1) / CHUNKS;       // 18797
    const int lo  = ch * per;
    const int hi  = min(lo + per, N4);

    if (tid == 0) {
        cnt   = 0;
        thr64 = 0ull;
        guard = -__int_as_float(0x7F800000);          // -inf
    }
    __syncthreads();

    #pragma unroll 1
    for (int t0 = lo; t0 < hi; t0 += T1) {
        const int i = t0 + tid;
        if (i < hi) {
            float4 v = base[i];
            const float g = guard;
            const float m = fmaxf(fmaxf(v.x, v.y), fmaxf(v.z, v.w));
            if (m > g) {                               // rare after warmup
                const unsigned long long th = thr64;
                const int idx0 = i * 4;
                // full-precision candidate keys (same function used everywhere)
                unsigned long long p0 = pack(ref_sigmoid(v.x), idx0 + 0);
                unsigned long long p1 = pack(ref_sigmoid(v.y), idx0 + 1);
                unsigned long long p2 = pack(ref_sigmoid(v.z), idx0 + 2);
                unsigned long long p3 = pack(ref_sigmoid(v.w), idx0 + 3);
                if (p0 > th) { int p = atomicAdd(&cnt, 1); buf[p] = p0; }
                if (p1 > th) { int p = atomicAdd(&cnt, 1); buf[p] = p1; }
                if (p2 > th) { int p = atomicAdd(&cnt, 1); buf[p] = p2; }
                if (p3 > th) { int p = atomicAdd(&cnt, 1); buf[p] = p3; }
            }
        }
        __syncthreads();
        // next tile can append up to 4*T1 = 2048 entries; prune if low on room
        if (cnt > BUF - 4 * T1) {
            const int c = min(cnt, BUF);
            for (int p = c + tid; p < BUF; p += T1) buf[p] = 0ull;
            __syncthreads();
            bitonic_desc<BUF, T1>(buf, tid);
            if (tid == 0) {
                cnt   = KEEP;
                thr64 = buf[KEEP - 1];
                // conservative logit guard: sigma^-1(thr_prob) minus margin that
                // covers mufu wiggle (<=5e-4 abs) over the steepest local slope
                float pth = __uint_as_float((unsigned int)(buf[KEEP - 1] >> 32));
                pth = fminf(fmaxf(pth, 1e-6f), 1.0f - 1e-6f);
                guard = logf(pth / (1.0f - pth)) - 0.15f;
            }
            __syncthreads();
        }
    }

    // final sort + emit top-KEEP of this chunk
    {
        const int c = min(cnt, BUF);
        for (int p = c + tid; p < BUF; p += T1) buf[p] = 0ull;
        __syncthreads();
        bitonic_desc<BUF, T1>(buf, tid);
        unsigned long long* dst = g_cand + ((size_t)b * CHUNKS + ch) * KEEP;
        for (int p = tid; p < KEEP; p += T1) dst[p] = buf[p];
    }
}

// ---------------------------------------------------------------------------
// Kernel 2: per-batch merge of pre-keyed candidates -> final outputs
// out layout (float32): scores[B*K] | labels[B*K] | boxes[B*K*4]
// ---------------------------------------------------------------------------
__global__ __launch_bounds__(T2, 1)
void topk_merge_kernel(const float* __restrict__ bbox,
                       const float* __restrict__ tsz,
                       float* __restrict__ out) {
    __shared__ unsigned long long s[MERGE_N];
    const int b   = blockIdx.x;
    const int tid = threadIdx.x;
    const int tot = CHUNKS * KEEP;                     // 3072

    const unsigned long long* src = g_cand + (size_t)b * tot;
    #pragma unroll
    for (int i = tid; i < MERGE_N; i += T2)
        s[i] = (i < tot) ? src[i] : 0ull;
    __syncthreads();

    bitonic_desc<MERGE_N, T2>(s, tid);

    if (tid < KTOP) {
        const unsigned long long cb = s[tid];
        const float score = __uint_as_float((unsigned int)(cb >> 32));
        const unsigned int idx = ~(unsigned int)cb;

        const int q   = (int)(idx / CN);
        const int lab = (int)(idx % CN);

        const float4 bx = reinterpret_cast<const float4*>(bbox)[b * QN + q];
        const float x0 = bx.x - 0.5f * bx.z;
        const float y0 = bx.y - 0.5f * bx.w;
        const float x1 = bx.x + 0.5f * bx.z;
        const float y1 = bx.y + 0.5f * bx.w;

        const float ih = tsz[b * 2 + 0];
        const float iw = tsz[b * 2 + 1];

        out[b * KTOP + tid] = score;                          // scores
        out[BATCH * KTOP + b * KTOP + tid] = (float)lab;      // labels
        float* bo = out + 2 * BATCH * KTOP + (size_t)(b * KTOP + tid) * 4;
        bo[0] = x0 * iw;
        bo[1] = y0 * ih;
        bo[2] = x1 * iw;
        bo[3] = y1 * ih;
    }
}

extern "C" void kernel_launch(void* const* d_in, const int* in_sizes, int n_in,
                              void* d_out, int out_size) {
    const float* logits = (const float*)d_in[0];   // (64,1000,1203) f32
    const float* bbox   = (const float*)d_in[1];   // (64,1000,4)    f32
    const float* tsz    = (const float*)d_in[2];   // (64,2)         f32
    float* out          = (float*)d_out;           // 38400 f32

    dim3 g1(CHUNKS, BATCH);
    topk_chunk_kernel<<<g1, T1>>>(logits);
    topk_merge_kernel<<<BATCH, T2>>>(bbox, tsz, out);
}

// round 4
// speedup vs baseline: 1.5565x; 1.5565x over previous
#include <cuda_runtime.h>
#include <cstdint>

#define BATCH   64
#define QN      1000
#define CN      1203
#define NTOT    (QN * CN)        // 1203000 per batch
#define N4      (NTOT / 4)       // 300750 float4 per batch
#define KTOP    100
#define KEEP    128              // survivors per chunk
#define CHUNKS  16
#define T1      512              // threads, chunk kernel
#define BUF     5120             // shared candidate buffer (u64) = 40KB
#define TILE_F4 (2 * T1)         // 1024 float4 = 4096 floats per tile
#define T2      256              // threads, merge kernel
#define MN      (CHUNKS * KEEP)  // 2048

#define NEG_INF (-__int_as_float(0x7F800000))

// per-chunk candidates, unsorted: packed (mufu_prob_bits<<32)|~idx
__device__ unsigned long long g_cand[BATCH * CHUNKS * KEEP];

// Reference sigmoid: XLA-GPU logistic -> 0.5 + 0.5*tanh.approx(0.5*x)
__device__ __forceinline__ float ref_sigmoid(float x) {
    float t;
    asm("tanh.approx.f32 %0, %1;" : "=f"(t) : "f"(x * 0.5f));
    return fmaf(0.5f, t, 0.5f);
}

__device__ __forceinline__ unsigned long long packkey(float prob, int idx) {
    return ((unsigned long long)__float_as_uint(prob) << 32)
         | (unsigned int)(~idx);          // smaller idx wins ties
}

// conservative logit-space guard: x <= guard  =>  mufu_prob(x) < thr_prob
__device__ __forceinline__ float guard_from_thr(unsigned long long thr) {
    float p  = __uint_as_float((unsigned int)(thr >> 32));
    float pf = p - 2e-3f;                 // >= 3x mufu tanh abs-error bound
    if (pf <= 1e-7f) return NEG_INF;
    if (pf >= 1.0f - 1e-7f) pf = 1.0f - 1e-7f;
    return __logf(pf / (1.0f - pf)) - 2e-2f;
}

// exact k-th largest u64 among s[0..n), 8-bit MSD radix descent
template <int NTHR>
__device__ unsigned long long radix_kth(const unsigned long long* s, int n, int k,
                                        int* hist, unsigned long long* sh_pref,
                                        int* sh_k, int tid) {
    unsigned long long prefix = 0, mask = 0;
    int kk = k;
    #pragma unroll 1
    for (int shift = 56; shift >= 0; shift -= 8) {
        for (int i = tid; i < 256; i += NTHR) hist[i] = 0;
        __syncthreads();
        #pragma unroll 1
        for (int i = tid; i < n; i += NTHR) {
            unsigned long long v = s[i];
            if ((v & mask) == prefix)
                atomicAdd(&hist[(int)((v >> shift) & 255)], 1);
        }
        __syncthreads();
        if (tid == 0) {
            int rem = kk;
            int d = 255;
            for (; d > 0; --d) {
                int h = hist[d];
                if (rem <= h) break;
                rem -= h;
            }
            *sh_k = rem;
            *sh_pref = prefix | ((unsigned long long)d << shift);
        }
        __syncthreads();
        prefix = *sh_pref;
        kk = *sh_k;
        mask |= (0xFFull << shift);
        __syncthreads();
    }
    return prefix;
}

// in-place compact keeping elements >= thr (unique keys => exact count)
template <int NTHR, int MAXPER>
__device__ int compact_ge(unsigned long long* s, int n, unsigned long long thr,
                          int* sh_cnt, int tid) {
    unsigned long long mine[MAXPER];
    int nm = 0;
    #pragma unroll 1
    for (int i = tid; i < n; i += NTHR) {
        unsigned long long v = s[i];
        if (v >= thr) mine[nm++] = v;
    }
    __syncthreads();
    if (tid == 0) *sh_cnt = 0;
    __syncthreads();
    if (nm) {
        int p = atomicAdd(sh_cnt, nm);
        for (int j = 0; j < nm; j++) s[p + j] = mine[j];
    }
    __syncthreads();
    return *sh_cnt;
}

template <int NSORT, int NTHREADS>
__device__ __forceinline__ void bitonic_desc(unsigned long long* s, int tid) {
    #pragma unroll 1
    for (int k = 2; k <= NSORT; k <<= 1) {
        #pragma unroll 1
        for (int j = k >> 1; j > 0; j >>= 1) {
            for (int i = tid; i < NSORT; i += NTHREADS) {
                int ixj = i ^ j;
                if (ixj > i) {
                    unsigned long long a = s[i], b = s[ixj];
                    if ((a < b) == ((i & k) == 0)) { s[i] = b; s[ixj] = a; }
                }
            }
            __syncthreads();
        }
    }
}

// ---------------------------------------------------------------------------
// Kernel 1: per (batch, chunk) streaming top-KEEP, radix-select pruning
// ---------------------------------------------------------------------------
__global__ __launch_bounds__(T1, 2)
void topk_chunk_kernel(const float* __restrict__ logits) {
    __shared__ unsigned long long buf[BUF];
    __shared__ int hist[256];
    __shared__ unsigned long long sh_pref;
    __shared__ int sh_k;
    __shared__ int cnt;
    __shared__ unsigned long long thr64_s;
    __shared__ float guard_s;

    const int b    = blockIdx.y;
    const int ch   = blockIdx.x;
    const int tid  = threadIdx.x;
    const int lane = tid & 31;

    const float4* __restrict__ base =
        reinterpret_cast<const float4*>(logits + (size_t)b * NTOT);

    const int per = (N4 + CHUNKS - 1) / CHUNKS;
    const int lo  = ch * per;
    const int hi  = min(lo + per, N4);

    if (tid == 0) { cnt = 0; thr64_s = 0ull; guard_s = NEG_INF; }
    __syncthreads();

    #pragma unroll 1
    for (int t0 = lo; t0 < hi; t0 += TILE_F4) {
        const int i0 = t0 + tid;
        const int i1 = t0 + T1 + tid;
        float4 v0 = make_float4(NEG_INF, NEG_INF, NEG_INF, NEG_INF);
        float4 v1 = v0;
        if (i0 < hi) v0 = base[i0];
        if (i1 < hi) v1 = base[i1];

        const float g = guard_s;
        const float m = fmaxf(fmaxf(fmaxf(v0.x, v0.y), fmaxf(v0.z, v0.w)),
                              fmaxf(fmaxf(v1.x, v1.y), fmaxf(v1.z, v1.w)));

        if (__any_sync(0xFFFFFFFFu, m > g)) {         // warp-level slow path
            const unsigned long long th = thr64_s;
            unsigned long long loc[8];
            int nl = 0;
            if (m > g) {
                const int x0 = i0 * 4, x1 = i1 * 4;
                unsigned long long k;
                if (v0.x > g) { k = packkey(ref_sigmoid(v0.x), x0 + 0); if (k > th) loc[nl++] = k; }
                if (v0.y > g) { k = packkey(ref_sigmoid(v0.y), x0 + 1); if (k > th) loc[nl++] = k; }
                if (v0.z > g) { k = packkey(ref_sigmoid(v0.z), x0 + 2); if (k > th) loc[nl++] = k; }
                if (v0.w > g) { k = packkey(ref_sigmoid(v0.w), x0 + 3); if (k > th) loc[nl++] = k; }
                if (v1.x > g) { k = packkey(ref_sigmoid(v1.x), x1 + 0); if (k > th) loc[nl++] = k; }
                if (v1.y > g) { k = packkey(ref_sigmoid(v1.y), x1 + 1); if (k > th) loc[nl++] = k; }
                if (v1.z > g) { k = packkey(ref_sigmoid(v1.z), x1 + 2); if (k > th) loc[nl++] = k; }
                if (v1.w > g) { k = packkey(ref_sigmoid(v1.w), x1 + 3); if (k > th) loc[nl++] = k; }
            }
            // warp-aggregated append: one shared atomic per warp
            int pre = nl;
            #pragma unroll
            for (int o = 1; o < 32; o <<= 1) {
                int u = __shfl_up_sync(0xFFFFFFFFu, pre, o);
                if (lane >= o) pre += u;
            }
            int tot = __shfl_sync(0xFFFFFFFFu, pre, 31);
            int bpos = 0;
            if (tot > 0) {
                if (lane == 31) bpos = atomicAdd(&cnt, tot);
                bpos = __shfl_sync(0xFFFFFFFFu, bpos, 31);
                const int p = bpos + pre - nl;
                for (int j = 0; j < nl; j++) buf[p + j] = loc[j];
            }
        }
        __syncthreads();

        if (cnt > BUF - 8 * T1) {                     // prune (rare)
            const int n = cnt;
            unsigned long long kth =
                radix_kth<T1>(buf, n, KEEP, hist, &sh_pref, &sh_k, tid);
            compact_ge<T1, (BUF + T1 - 1) / T1>(buf, n, kth, &cnt, tid);
            if (tid == 0) {
                thr64_s = kth;
                guard_s = guard_from_thr(kth);
            }
            __syncthreads();
        }
    }

    // final: exact top-KEEP, unsorted
    {
        const int n = cnt;
        unsigned long long kth =
            radix_kth<T1>(buf, n, KEEP, hist, &sh_pref, &sh_k, tid);
        compact_ge<T1, (BUF + T1 - 1) / T1>(buf, n, kth, &cnt, tid);
        unsigned long long* dst = g_cand + ((size_t)b * CHUNKS + ch) * KEEP;
        for (int p = tid; p < KEEP; p += T1) dst[p] = buf[p];
    }
}

// ---------------------------------------------------------------------------
// Kernel 2: per-batch merge: radix-select top-100, tiny sort, emit
// out layout (float32): scores[B*K] | labels[B*K] | boxes[B*K*4]
// ---------------------------------------------------------------------------
__global__ __launch_bounds__(T2, 4)
void topk_merge_kernel(const float* __restrict__ bbox,
                       const float* __restrict__ tsz,
                       float* __restrict__ out) {
    __shared__ unsigned long long s[MN];
    __shared__ int hist[256];
    __shared__ unsigned long long sh_pref;
    __shared__ int sh_k;
    __shared__ int sc;

    const int b   = blockIdx.x;
    const int tid = threadIdx.x;

    const unsigned long long* src = g_cand + (size_t)b * MN;
    #pragma unroll
    for (int i = tid; i < MN; i += T2) s[i] = src[i];
    __syncthreads();

    unsigned long long kth =
        radix_kth<T2>(s, MN, KTOP, hist, &sh_pref, &sh_k, tid);
    compact_ge<T2, (MN + T2 - 1) / T2>(s, MN, kth, &sc, tid);   // exactly 100

    for (int i = KTOP + tid; i < 128; i += T2) s[i] = 0ull;     // pad to 128
    __syncthreads();

    bitonic_desc<128, T2>(s, tid);

    if (tid < KTOP) {
        const unsigned long long cb = s[tid];
        const float score = __uint_as_float((unsigned int)(cb >> 32));
        const unsigned int idx = ~(unsigned int)cb;

        const int q   = (int)(idx / CN);
        const int lab = (int)(idx % CN);

        const float4 bx = reinterpret_cast<const float4*>(bbox)[b * QN + q];
        const float x0 = bx.x - 0.5f * bx.z;
        const float y0 = bx.y - 0.5f * bx.w;
        const float x1 = bx.x + 0.5f * bx.z;
        const float y1 = bx.y + 0.5f * bx.w;

        const float ih = tsz[b * 2 + 0];
        const float iw = tsz[b * 2 + 1];

        out[b * KTOP + tid] = score;                          // scores
        out[BATCH * KTOP + b * KTOP + tid] = (float)lab;      // labels
        float* bo = out + 2 * BATCH * KTOP + (size_t)(b * KTOP + tid) * 4;
        bo[0] = x0 * iw;
        bo[1] = y0 * ih;
        bo[2] = x1 * iw;
        bo[3] = y1 * ih;
    }
}

extern "C" void kernel_launch(void* const* d_in, const int* in_sizes, int n_in,
                              void* d_out, int out_size) {
    const float* logits = (const float*)d_in[0];   // (64,1000,1203) f32
    const float* bbox   = (const float*)d_in[1];   // (64,1000,4)    f32
    const float* tsz    = (const float*)d_in[2];   // (64,2)         f32
    float* out          = (float*)d_out;           // 38400 f32

    dim3 g1(CHUNKS, BATCH);
    topk_chunk_kernel<<<g1, T1>>>(logits);
    topk_merge_kernel<<<BATCH, T2>>>(bbox, tsz, out);
}

// round 5
// speedup vs baseline: 3.9341x; 2.5275x over previous
#include <cuda_runtime.h>
#include <cstdint>

#define BATCH   64
#define QN      1000
#define CN      1203
#define NTOT    (QN * CN)        // 1203000 per batch
#define N4      (NTOT / 4)       // 300750 float4 per batch
#define KTOP    100
#define KEEP    128              // survivors per chunk
#define CHUNKS  9
#define T1      512              // threads, chunk kernel
#define VPT     4                // float4 per thread per tile
#define TILE_F4 (VPT * T1)       // 2048 float4 = 8192 floats per tile
#define BUF     10240            // shared candidate buffer (u64) = 80KB
#define T2      256              // threads, merge kernel
#define MN      (CHUNKS * KEEP)  // 1152

#define NEG_INF (-__int_as_float(0x7F800000))

typedef unsigned long long u64;

// per-chunk candidates, unsorted: packed (mufu_prob_bits<<32)|~idx
__device__ u64 g_cand[BATCH * CHUNKS * KEEP];

// Reference sigmoid: XLA-GPU logistic -> 0.5 + 0.5*tanh.approx(0.5*x)
__device__ __forceinline__ float ref_sigmoid(float x) {
    float t;
    asm("tanh.approx.f32 %0, %1;" : "=f"(t) : "f"(x * 0.5f));
    return fmaf(0.5f, t, 0.5f);
}

__device__ __forceinline__ u64 packkey(float prob, int idx) {
    return ((u64)__float_as_uint(prob) << 32) | (unsigned int)(~idx);
}

// conservative logit guard: x <= guard => mufu_prob(x) < thr_prob
__device__ __forceinline__ float guard_from_thr(u64 thr) {
    float p  = __uint_as_float((unsigned int)(thr >> 32));
    float pf = p - 2e-3f;                 // >= 3x mufu tanh abs-error bound
    if (pf <= 1e-7f) return NEG_INF;
    if (pf >= 1.0f - 1e-7f) pf = 1.0f - 1e-7f;
    return __logf(pf / (1.0f - pf)) - 2e-2f;
}

// shared workspace for selection
struct SelWS {
    int hist[256];
    int suff[257];
    int wsum[8];
    u64 sh_pref;
    int sh_k;
    int sh_cnt;
};

// exact k-th largest u64 among s[0..n): 8-bit MSD radix descent,
// parallel (warp-shuffle) suffix-scan digit selection.
template <int NTHR>
__device__ u64 radix_kth(const u64* s, int n, int k, SelWS* w, int tid) {
    const int lane = tid & 31;
    u64 prefix = 0, mask = 0;
    int kk = k;
    #pragma unroll 1
    for (int shift = 56; shift >= 0; shift -= 8) {
        for (int i = tid; i < 256; i += NTHR) w->hist[i] = 0;
        __syncthreads();
        #pragma unroll 1
        for (int i = tid; i < n; i += NTHR) {
            u64 v = s[i];
            if ((v & mask) == prefix)
                atomicAdd(&w->hist[(int)((v >> shift) & 255)], 1);
        }
        __syncthreads();
        int ss = 0;
        if (tid < 256) {
            ss = w->hist[tid];
            #pragma unroll
            for (int o = 1; o < 32; o <<= 1) {
                int u = __shfl_down_sync(0xFFFFFFFFu, ss, o);
                if (lane + o < 32) ss += u;
            }
            if (lane == 0) w->wsum[tid >> 5] = ss;    // whole-warp sum
        }
        __syncthreads();
        if (tid == 0) {
            int acc = 0;
            #pragma unroll
            for (int wi = 7; wi >= 0; --wi) {         // wsum[wi] -> sum of warps > wi
                int t = w->wsum[wi];
                w->wsum[wi] = acc;
                acc += t;
            }
            w->suff[256] = 0;
        }
        __syncthreads();
        if (tid < 256) w->suff[tid] = ss + w->wsum[tid >> 5];  // count(digit >= tid)
        __syncthreads();
        if (tid < 256) {
            int GE = w->suff[tid], GT = w->suff[tid + 1];
            if (GT < kk && kk <= GE) {
                w->sh_k = kk - GT;
                w->sh_pref = prefix | ((u64)tid << shift);
            }
        }
        __syncthreads();
        prefix = w->sh_pref;
        kk = w->sh_k;
        mask |= (0xFFull << shift);
        __syncthreads();
    }
    return prefix;
}

// compact elements >= thr into stage[0..k) (u64 keys unique => exactly k matches)
template <int NTHR>
__device__ int compact_ge(const u64* s, int n, u64 thr, u64* stage,
                          int* sh_cnt, int tid) {
    if (tid == 0) *sh_cnt = 0;
    __syncthreads();
    #pragma unroll 1
    for (int i = tid; i < n; i += NTHR) {
        u64 v = s[i];
        if (v >= thr) stage[atomicAdd(sh_cnt, 1)] = v;
    }
    __syncthreads();
    return *sh_cnt;
}

template <int NSORT, int NTHREADS>
__device__ __forceinline__ void bitonic_desc(u64* s, int tid) {
    #pragma unroll 1
    for (int k = 2; k <= NSORT; k <<= 1) {
        #pragma unroll 1
        for (int j = k >> 1; j > 0; j >>= 1) {
            for (int i = tid; i < NSORT; i += NTHREADS) {
                int ixj = i ^ j;
                if (ixj > i) {
                    u64 a = s[i], b = s[ixj];
                    if ((a < b) == ((i & k) == 0)) { s[i] = b; s[ixj] = a; }
                }
            }
            __syncthreads();
        }
    }
}

// ballot-aggregated shared append of one predicate'd value per lane
__device__ __forceinline__ void warp_append(u64* buf, int* cnt, bool pass,
                                            u64 key, int lane) {
    unsigned bal = __ballot_sync(0xFFFFFFFFu, pass);
    if (bal) {
        int leader = __ffs(bal) - 1;
        int bpos = 0;
        if (lane == leader) bpos = atomicAdd(cnt, __popc(bal));
        bpos = __shfl_sync(0xFFFFFFFFu, bpos, leader);
        if (pass) buf[bpos + __popc(bal & ((1u << lane) - 1u))] = key;
    }
}

// ---------------------------------------------------------------------------
// Kernel 1: per (batch, chunk) streaming top-KEEP
// ---------------------------------------------------------------------------
__global__ __launch_bounds__(T1, 2)
void topk_chunk_kernel(const float* __restrict__ logits) {
    __shared__ u64 buf[BUF];
    __shared__ u64 stage[KEEP];
    __shared__ SelWS ws;
    __shared__ int cnt;
    __shared__ u64 thr64_s;
    __shared__ float guard_s;

    const int b    = blockIdx.y;
    const int ch   = blockIdx.x;
    const int tid  = threadIdx.x;
    const int lane = tid & 31;

    const float4* __restrict__ base =
        reinterpret_cast<const float4*>(logits + (size_t)b * NTOT);

    const int per = (N4 + CHUNKS - 1) / CHUNKS;   // 33417
    const int lo  = ch * per;
    const int hi  = min(lo + per, N4);

    if (tid == 0) { cnt = 0; thr64_s = 0ull; guard_s = NEG_INF; }
    __syncthreads();

    #pragma unroll 1
    for (int t0 = lo; t0 < hi; t0 += TILE_F4) {
        float4 v[VPT];
        int    ix[VPT];
        #pragma unroll
        for (int j = 0; j < VPT; j++) {
            const int i = t0 + j * T1 + tid;
            ix[j] = i;
            v[j] = (i < hi) ? base[i]
                            : make_float4(NEG_INF, NEG_INF, NEG_INF, NEG_INF);
        }
        const float g = guard_s;
        float m = NEG_INF;
        #pragma unroll
        for (int j = 0; j < VPT; j++)
            m = fmaxf(m, fmaxf(fmaxf(v[j].x, v[j].y), fmaxf(v[j].z, v[j].w)));

        if (__any_sync(0xFFFFFFFFu, m > g)) {      // warp-level slow path
            const u64 th = thr64_s;
            #pragma unroll
            for (int j = 0; j < VPT; j++) {
                const int x0 = ix[j] * 4;
                const float f[4] = {v[j].x, v[j].y, v[j].z, v[j].w};
                #pragma unroll
                for (int e = 0; e < 4; e++) {
                    bool pre = f[e] > g;
                    u64 key = 0;
                    if (pre) key = packkey(ref_sigmoid(f[e]), x0 + e);
                    warp_append(buf, &cnt, pre && key > th, key, lane);
                }
            }
        }
        __syncthreads();

        if (cnt > BUF - 4 * TILE_F4) {             // prune (≈ once per CTA)
            const int n = min(cnt, BUF);
            u64 kth = radix_kth<T1>(buf, n, KEEP, &ws, tid);
            compact_ge<T1>(buf, n, kth, stage, &ws.sh_cnt, tid);
            for (int p = tid; p < KEEP; p += T1) buf[p] = stage[p];
            if (tid == 0) {
                cnt     = KEEP;
                thr64_s = kth;
                guard_s = guard_from_thr(kth);
            }
            __syncthreads();
        }
    }

    // final: exact top-KEEP (unsorted) straight to gmem
    {
        const int n = min(cnt, BUF);
        u64 kth = radix_kth<T1>(buf, n, KEEP, &ws, tid);
        compact_ge<T1>(buf, n, kth, stage, &ws.sh_cnt, tid);
        u64* dst = g_cand + ((size_t)b * CHUNKS + ch) * KEEP;
        for (int p = tid; p < KEEP; p += T1) dst[p] = stage[p];
    }
}

// ---------------------------------------------------------------------------
// Kernel 2: per-batch merge: radix-select top-100, tiny sort, emit
// out layout (float32): scores[B*K] | labels[B*K] | boxes[B*K*4]
// ---------------------------------------------------------------------------
__global__ __launch_bounds__(T2, 4)
void topk_merge_kernel(const float* __restrict__ bbox,
                       const float* __restrict__ tsz,
                       float* __restrict__ out) {
    __shared__ u64 s[MN];
    __shared__ u64 stage[128];
    __shared__ SelWS ws;

    const int b   = blockIdx.x;
    const int tid = threadIdx.x;

    const u64* src = g_cand + (size_t)b * MN;
    #pragma unroll
    for (int i = tid; i < MN; i += T2) s[i] = src[i];
    __syncthreads();

    u64 kth = radix_kth<T2>(s, MN, KTOP, &ws, tid);
    compact_ge<T2>(s, MN, kth, stage, &ws.sh_cnt, tid);   // exactly 100

    for (int i = KTOP + tid; i < 128; i += T2) stage[i] = 0ull;
    __syncthreads();

    bitonic_desc<128, T2>(stage, tid);

    if (tid < KTOP) {
        const u64 cb = stage[tid];
        const float score = __uint_as_float((unsigned int)(cb >> 32));
        const unsigned int idx = ~(unsigned int)cb;

        const int q   = (int)(idx / CN);
        const int lab = (int)(idx % CN);

        const float4 bx = reinterpret_cast<const float4*>(bbox)[b * QN + q];
        const float x0 = bx.x - 0.5f * bx.z;
        const float y0 = bx.y - 0.5f * bx.w;
        const float x1 = bx.x + 0.5f * bx.z;
        const float y1 = bx.y + 0.5f * bx.w;

        const float ih = tsz[b * 2 + 0];
        const float iw = tsz[b * 2 + 1];

        out[b * KTOP + tid] = score;                          // scores
        out[BATCH * KTOP + b * KTOP + tid] = (float)lab;      // labels
        float* bo = out + 2 * BATCH * KTOP + (size_t)(b * KTOP + tid) * 4;
        bo[0] = x0 * iw;
        bo[1] = y0 * ih;
        bo[2] = x1 * iw;
        bo[3] = y1 * ih;
    }
}

extern "C" void kernel_launch(void* const* d_in, const int* in_sizes, int n_in,
                              void* d_out, int out_size) {
    const float* logits = (const float*)d_in[0];   // (64,1000,1203) f32
    const float* bbox   = (const float*)d_in[1];   // (64,1000,4)    f32
    const float* tsz    = (const float*)d_in[2];   // (64,2)         f32
    float* out          = (float*)d_out;           // 38400 f32

    dim3 g1(CHUNKS, BATCH);
    topk_chunk_kernel<<<g1, T1>>>(logits);
    topk_merge_kernel<<<BATCH, T2>>>(bbox, tsz, out);
}

// round 6
// speedup vs baseline: 4.2540x; 1.0813x over previous
#include <cuda_runtime.h>
#include <cstdint>

#define BATCH   64
#define QN      1000
#define CN      1203
#define NTOT    (QN * CN)          // 1203000 per batch
#define N4      (NTOT / 4)         // 300750 float4 per batch
#define KTOP    100
#define KEEP    128                // survivors per chunk
#define CHUNKS  4
#define T1      512
#define VPT     4                  // float4 per thread per tile
#define TILE_F4 (VPT * T1)         // 2048 float4 = 8192 floats
#define BUF     12288              // 96KB shared candidate buffer
#define WATERMARK (BUF - 4 * TILE_F4)   // 4096: cnt<=WM + 8192 appends <= BUF
#define MN      (CHUNKS * KEEP)    // 512 merge candidates per batch

#define NEG_INF (-__int_as_float(0x7F800000))

typedef unsigned long long u64;

__device__ u64 g_cand[BATCH * CHUNKS * KEEP];
__device__ int g_done[BATCH];      // zero-init; self-resetting per launch

// Reference sigmoid: XLA-GPU logistic -> 0.5 + 0.5*tanh.approx(0.5*x)
__device__ __forceinline__ float ref_sigmoid(float x) {
    float t;
    asm("tanh.approx.f32 %0, %1;" : "=f"(t) : "f"(x * 0.5f));
    return fmaf(0.5f, t, 0.5f);
}

__device__ __forceinline__ u64 packprob(float p, int idx) {
    return ((u64)__float_as_uint(p) << 32) | (unsigned)(~idx);
}
__device__ __forceinline__ u64 packlogit(float x, int idx) {
    unsigned bits = __float_as_uint(x);
    bits = (bits & 0x80000000u) ? ~bits : (bits | 0x80000000u);
    return ((u64)bits << 32) | (unsigned)(~idx);
}
__device__ __forceinline__ float ord2f(unsigned k) {
    unsigned x = (k & 0x80000000u) ? (k & 0x7FFFFFFFu) : ~k;
    return __uint_as_float(x);
}

// conservative logit guard: x <= guard => mufu_prob(x) < p (with margin)
__device__ __forceinline__ float guard_from_prob(float p) {
    float pf = p - 2e-3f;              // >= 3x mufu tanh abs-error bound
    if (pf <= 1e-7f) return NEG_INF;
    if (pf >= 1.0f - 1e-7f) pf = 1.0f - 1e-7f;
    return __logf(pf / (1.0f - pf)) - 2e-2f;
}

struct SelWS {
    int hist[256];
    int suff[257];
    int wsum[8];
    u64 sh_pref;
    u64 minkey;
    int sh_k;
    int flag;
    int sh_cnt;
};

// exact k-th largest u64 among s[0..n): MSD radix descent with
// match-aggregated histograms and early exit (kk == bin count -> min scan).
template <int NTHR>
__device__ u64 radix_kth(const u64* s, int n, int k, SelWS* w, int tid) {
    const int lane = tid & 31;
    u64 prefix = 0, mask = 0;
    int kk = k;
    #pragma unroll 1
    for (int shift = 56; shift >= 0; shift -= 8) {
        if (tid < 256) w->hist[tid] = 0;
        if (tid == 0) w->flag = 0;
        __syncthreads();
        // count (warp-uniform loop bound so sync collectives are legal)
        #pragma unroll 1
        for (int i = tid; (i - lane) < n; i += NTHR) {
            u64 v = (i < n) ? s[i] : 0ull;
            bool act = (i < n) && ((v & mask) == prefix);
            unsigned grp = __ballot_sync(0xFFFFFFFFu, act);
            if (act) {
                int d = (int)((v >> shift) & 255);
                unsigned peers = __match_any_sync(grp, d);
                if (lane == __ffs(peers) - 1)
                    atomicAdd(&w->hist[d], __popc(peers));
            }
        }
        __syncthreads();
        // suffix scan of 256 bins (8 warps of the first 256 threads)
        int ss = 0;
        if (tid < 256) {
            ss = w->hist[tid];
            #pragma unroll
            for (int o = 1; o < 32; o <<= 1) {
                int u = __shfl_down_sync(0xFFFFFFFFu, ss, o);
                if (lane + o < 32) ss += u;
            }
            if (lane == 0) w->wsum[tid >> 5] = ss;
        }
        __syncthreads();
        if (tid == 0) {
            int acc = 0;
            #pragma unroll
            for (int wi = 7; wi >= 0; --wi) { int t = w->wsum[wi]; w->wsum[wi] = acc; acc += t; }
            w->suff[256] = 0;
        }
        __syncthreads();
        if (tid < 256) w->suff[tid] = ss + w->wsum[tid >> 5];
        __syncthreads();
        if (tid < 256) {
            int GE = w->suff[tid], GT = w->suff[tid + 1];
            if (GT < kk && kk <= GE) {
                w->sh_k = kk - GT;
                w->sh_pref = prefix | ((u64)tid << shift);
                w->flag = ((kk - GT) == (GE - GT)) ? 1 : 0;   // kk' == bin count
            }
        }
        __syncthreads();
        prefix = w->sh_pref;
        kk = w->sh_k;
        mask |= (0xFFull << shift);
        if (w->flag || shift == 0) {
            // kth = min over elements matching prefix under mask
            if (tid == 0) w->minkey = ~0ull;
            __syncthreads();
            u64 lm = ~0ull;
            #pragma unroll 1
            for (int i = tid; i < n; i += NTHR) {
                u64 v = s[i];
                if ((v & mask) == prefix) lm = min(lm, v);
            }
            #pragma unroll
            for (int o = 16; o > 0; o >>= 1)
                lm = min(lm, __shfl_down_sync(0xFFFFFFFFu, lm, o));
            if (lane == 0) atomicMin(&w->minkey, lm);
            __syncthreads();
            return w->minkey;
        }
        __syncthreads();
    }
    return prefix;
}

template <int NTHR>
__device__ void compact_ge(const u64* s, int n, u64 thr, u64* dst,
                           int* sh_cnt, int tid) {
    if (tid == 0) *sh_cnt = 0;
    __syncthreads();
    #pragma unroll 1
    for (int i = tid; i < n; i += NTHR) {
        u64 v = s[i];
        if (v >= thr) dst[atomicAdd(sh_cnt, 1)] = v;
    }
    __syncthreads();
}

template <int NSORT, int NTHREADS>
__device__ __forceinline__ void bitonic_desc(u64* s, int tid) {
    #pragma unroll 1
    for (int k = 2; k <= NSORT; k <<= 1) {
        #pragma unroll 1
        for (int j = k >> 1; j > 0; j >>= 1) {
            for (int i = tid; i < NSORT; i += NTHREADS) {
                int ixj = i ^ j;
                if (ixj > i) {
                    u64 a = s[i], b = s[ixj];
                    if ((a < b) == ((i & k) == 0)) { s[i] = b; s[ixj] = a; }
                }
            }
            __syncthreads();
        }
    }
}

__device__ __forceinline__ void warp_append(u64* buf, int* cnt, bool pass,
                                            u64 key, int lane) {
    unsigned bal = __ballot_sync(0xFFFFFFFFu, pass);
    if (bal) {
        int leader = __ffs(bal) - 1;
        int bpos = 0;
        if (lane == leader) bpos = atomicAdd(cnt, __popc(bal));
        bpos = __shfl_sync(0xFFFFFFFFu, bpos, leader);
        if (pass) buf[bpos + __popc(bal & ((1u << lane) - 1u))] = key;
    }
}

// ---------------------------------------------------------------------------
// Fused kernel: streaming top-KEEP per (batch, chunk); last CTA per batch merges
// out layout (float32): scores[B*K] | labels[B*K] | boxes[B*K*4]
// ---------------------------------------------------------------------------
__global__ __launch_bounds__(T1, 2)
void postproc_kernel(const float* __restrict__ logits,
                     const float* __restrict__ bbox,
                     const float* __restrict__ tsz,
                     float* __restrict__ out) {
    __shared__ u64 buf[BUF];
    __shared__ u64 stage[KEEP];
    __shared__ SelWS ws;
    __shared__ int cnt;
    __shared__ u64 thr64_s;
    __shared__ float guard_s;
    __shared__ int merge_flag;

    const int b    = blockIdx.y;
    const int ch   = blockIdx.x;
    const int tid  = threadIdx.x;
    const int lane = tid & 31;

    const float4* __restrict__ base =
        reinterpret_cast<const float4*>(logits + (size_t)b * NTOT);

    const int per = (N4 + CHUNKS - 1) / CHUNKS;   // 75188
    const int lo  = ch * per;
    const int hi  = min(lo + per, N4);

    // ---- Phase A: bulk-store tile 0 as raw logit keys -> derive guard ----
    {
        #pragma unroll
        for (int j = 0; j < VPT; j++) {
            const int i = lo + j * T1 + tid;
            float4 v = (i < hi) ? __ldcs(base + i)
                                : make_float4(NEG_INF, NEG_INF, NEG_INF, NEG_INF);
            const int x0 = i * 4;
            buf[(j * 4 + 0) * T1 + tid] = packlogit(v.x, x0 + 0);
            buf[(j * 4 + 1) * T1 + tid] = packlogit(v.y, x0 + 1);
            buf[(j * 4 + 2) * T1 + tid] = packlogit(v.z, x0 + 2);
            buf[(j * 4 + 3) * T1 + tid] = packlogit(v.w, x0 + 3);
        }
        __syncthreads();
        u64 kth = radix_kth<T1>(buf, 4 * TILE_F4, KEEP, &ws, tid);
        if (tid == 0) {
            const float L = ord2f((unsigned)(kth >> 32));
            const float p = 1.0f / (1.0f + expf(-L));   // accurate sigmoid
            guard_s = guard_from_prob(p);
            thr64_s = 0ull;
            cnt = 0;
        }
        __syncthreads();
    }

    // ---- Phase B: guarded streaming pass over the whole chunk ----
    #pragma unroll 1
    for (int t0 = lo; t0 < hi; t0 += TILE_F4) {
        float4 v[VPT];
        int    ix[VPT];
        #pragma unroll
        for (int j = 0; j < VPT; j++) {
            const int i = t0 + j * T1 + tid;
            ix[j] = i;
            v[j] = (i < hi) ? __ldcs(base + i)
                            : make_float4(NEG_INF, NEG_INF, NEG_INF, NEG_INF);
        }
        const float g = guard_s;
        float m = NEG_INF;
        #pragma unroll
        for (int j = 0; j < VPT; j++)
            m = fmaxf(m, fmaxf(fmaxf(v[j].x, v[j].y), fmaxf(v[j].z, v[j].w)));

        if (__any_sync(0xFFFFFFFFu, m > g)) {
            const u64 th = thr64_s;
            #pragma unroll
            for (int j = 0; j < VPT; j++) {
                const int x0 = ix[j] * 4;
                const float f0 = v[j].x, f1 = v[j].y, f2 = v[j].z, f3 = v[j].w;
                bool p0 = f0 > g, p1 = f1 > g, p2 = f2 > g, p3 = f3 > g;
                u64 k0 = 0, k1 = 0, k2 = 0, k3 = 0;
                if (p0) k0 = packprob(ref_sigmoid(f0), x0 + 0);
                if (p1) k1 = packprob(ref_sigmoid(f1), x0 + 1);
                if (p2) k2 = packprob(ref_sigmoid(f2), x0 + 2);
                if (p3) k3 = packprob(ref_sigmoid(f3), x0 + 3);
                warp_append(buf, &cnt, p0 && k0 > th, k0, lane);
                warp_append(buf, &cnt, p1 && k1 > th, k1, lane);
                warp_append(buf, &cnt, p2 && k2 > th, k2, lane);
                warp_append(buf, &cnt, p3 && k3 > th, k3, lane);
            }
        }
        __syncthreads();

        if (cnt > WATERMARK) {                 // prune (bounded: cnt <= BUF)
            u64 kth = radix_kth<T1>(buf, cnt, KEEP, &ws, tid);
            compact_ge<T1>(buf, cnt, kth, stage, &ws.sh_cnt, tid);
            for (int p = tid; p < KEEP; p += T1) buf[p] = stage[p];
            if (tid == 0) {
                cnt     = KEEP;
                thr64_s = kth;
                guard_s = guard_from_prob(__uint_as_float((unsigned)(kth >> 32)));
            }
            __syncthreads();
        }
    }

    // ---- final exact top-KEEP of this chunk -> g_cand (unsorted) ----
    {
        const int n = cnt;
        u64 kth = radix_kth<T1>(buf, n, KEEP, &ws, tid);
        compact_ge<T1>(buf, n, kth, stage, &ws.sh_cnt, tid);
        u64* dst = g_cand + ((size_t)b * CHUNKS + ch) * KEEP;
        for (int p = tid; p < KEEP; p += T1) dst[p] = stage[p];
    }

    // ---- last CTA of this batch performs the merge ----
    __threadfence();
    if (tid == 0) {
        int prev = atomicAdd(&g_done[b], 1);
        merge_flag = (prev == CHUNKS - 1);
        if (merge_flag) g_done[b] = 0;        // self-reset for graph replays
    }
    __syncthreads();
    if (!merge_flag) return;
    __threadfence();

    const u64* src = g_cand + (size_t)b * MN;
    for (int i = tid; i < MN; i += T1) buf[i] = src[i];
    __syncthreads();

    u64 kth = radix_kth<T1>(buf, MN, KTOP, &ws, tid);
    compact_ge<T1>(buf, MN, kth, stage, &ws.sh_cnt, tid);
    for (int i = KTOP + tid; i < KEEP; i += T1) stage[i] = 0ull;
    __syncthreads();

    bitonic_desc<KEEP, T1>(stage, tid);

    if (tid < KTOP) {
        const u64 cb = stage[tid];
        const float score = __uint_as_float((unsigned)(cb >> 32));
        const unsigned idx = ~(unsigned)cb;

        const int q   = (int)(idx / CN);
        const int lab = (int)(idx % CN);

        const float4 bx = reinterpret_cast<const float4*>(bbox)[b * QN + q];
        const float ih = tsz[b * 2 + 0];
        const float iw = tsz[b * 2 + 1];

        out[b * KTOP + tid] = score;                        // scores
        out[BATCH * KTOP + b * KTOP + tid] = (float)lab;    // labels
        float4 bo;
        bo.x = (bx.x - 0.5f * bx.z) * iw;
        bo.y = (bx.y - 0.5f * bx.w) * ih;
        bo.z = (bx.x + 0.5f * bx.z) * iw;
        bo.w = (bx.y + 0.5f * bx.w) * ih;
        reinterpret_cast<float4*>(out + 2 * BATCH * KTOP)[b * KTOP + tid] = bo;
    }
}

extern "C" void kernel_launch(void* const* d_in, const int* in_sizes, int n_in,
                              void* d_out, int out_size) {
    const float* logits = (const float*)d_in[0];   // (64,1000,1203) f32
    const float* bbox   = (const float*)d_in[1];   // (64,1000,4)    f32
    const float* tsz    = (const float*)d_in[2];   // (64,2)         f32
    float* out          = (float*)d_out;           // 38400 f32

    dim3 grid(CHUNKS, BATCH);
    postproc_kernel<<<grid, T1>>>(logits, bbox, tsz, out);
}

// round 7
// speedup vs baseline: 4.3077x; 1.0126x over previous
#include <cuda_runtime.h>
#include <cstdint>

#define BATCH   64
#define QN      1000
#define CN      1203
#define NTOT    (QN * CN)          // 1203000 per batch
#define N4      (NTOT / 4)         // 300750 float4 per batch
#define KTOP    100
#define KEEP    128                // survivors per chunk
#define CHUNKS  4
#define T1      512
#define VPT     4                  // float4 per thread per tile
#define TILE_F4 (VPT * T1)         // 2048 float4 = 8192 floats
#define BUF     12288              // 96KB shared candidate buffer
#define WATERMARK (BUF - 4 * TILE_F4)   // prune so worst-case tile fits
#define MN      (CHUNKS * KEEP)    // 512 merge candidates per batch

#define NEG_INF (-__int_as_float(0x7F800000))

typedef unsigned long long u64;

__device__ u64 g_cand[BATCH * CHUNKS * KEEP];
__device__ int g_done[BATCH];      // zero-init; self-resetting per launch

// Reference sigmoid: XLA-GPU logistic -> 0.5 + 0.5*tanh.approx(0.5*x)
__device__ __forceinline__ float ref_sigmoid(float x) {
    float t;
    asm("tanh.approx.f32 %0, %1;" : "=f"(t) : "f"(x * 0.5f));
    return fmaf(0.5f, t, 0.5f);
}

__device__ __forceinline__ u64 packprob(float p, int idx) {
    return ((u64)__float_as_uint(p) << 32) | (unsigned)(~idx);
}
__device__ __forceinline__ u64 packlogit(float x, int idx) {
    unsigned bits = __float_as_uint(x);
    bits = (bits & 0x80000000u) ? ~bits : (bits | 0x80000000u);
    return ((u64)bits << 32) | (unsigned)(~idx);
}
__device__ __forceinline__ float ord2f(unsigned k) {
    unsigned x = (k & 0x80000000u) ? (k & 0x7FFFFFFFu) : ~k;
    return __uint_as_float(x);
}

// conservative logit guard: x <= guard => mufu_prob(x) < p (with margin)
__device__ __forceinline__ float guard_from_prob(float p) {
    float pf = p - 2e-3f;              // >= 3x mufu tanh abs-error bound
    if (pf <= 1e-7f) return NEG_INF;
    if (pf >= 1.0f - 1e-7f) pf = 1.0f - 1e-7f;
    return __logf(pf / (1.0f - pf)) - 2e-2f;
}

struct SelWS {
    int hist[256];
    int suff[257];
    int wsum[8];
    u64 sh_pref;
    u64 minkey;
    int sh_k;
    int flag;
    int sh_cnt;
};

// exact k-th largest u64 among s[0..n): MSD radix descent with
// match-aggregated histograms and early exit.
template <int NTHR>
__device__ u64 radix_kth(const u64* s, int n, int k, SelWS* w, int tid) {
    const int lane = tid & 31;
    u64 prefix = 0, mask = 0;
    int kk = k;
    #pragma unroll 1
    for (int shift = 56; shift >= 0; shift -= 8) {
        if (tid < 256) w->hist[tid] = 0;
        if (tid == 0) w->flag = 0;
        __syncthreads();
        #pragma unroll 1
        for (int i = tid; (i - lane) < n; i += NTHR) {
            u64 v = (i < n) ? s[i] : 0ull;
            bool act = (i < n) && ((v & mask) == prefix);
            unsigned grp = __ballot_sync(0xFFFFFFFFu, act);
            if (act) {
                int d = (int)((v >> shift) & 255);
                unsigned peers = __match_any_sync(grp, d);
                if (lane == __ffs(peers) - 1)
                    atomicAdd(&w->hist[d], __popc(peers));
            }
        }
        __syncthreads();
        int ss = 0;
        if (tid < 256) {
            ss = w->hist[tid];
            #pragma unroll
            for (int o = 1; o < 32; o <<= 1) {
                int u = __shfl_down_sync(0xFFFFFFFFu, ss, o);
                if (lane + o < 32) ss += u;
            }
            if (lane == 0) w->wsum[tid >> 5] = ss;
        }
        __syncthreads();
        if (tid == 0) {
            int acc = 0;
            #pragma unroll
            for (int wi = 7; wi >= 0; --wi) { int t = w->wsum[wi]; w->wsum[wi] = acc; acc += t; }
            w->suff[256] = 0;
        }
        __syncthreads();
        if (tid < 256) w->suff[tid] = ss + w->wsum[tid >> 5];
        __syncthreads();
        if (tid < 256) {
            int GE = w->suff[tid], GT = w->suff[tid + 1];
            if (GT < kk && kk <= GE) {
                w->sh_k = kk - GT;
                w->sh_pref = prefix | ((u64)tid << shift);
                w->flag = ((kk - GT) == (GE - GT)) ? 1 : 0;
            }
        }
        __syncthreads();
        prefix = w->sh_pref;
        kk = w->sh_k;
        mask |= (0xFFull << shift);
        if (w->flag || shift == 0) {
            if (tid == 0) w->minkey = ~0ull;
            __syncthreads();
            u64 lm = ~0ull;
            #pragma unroll 1
            for (int i = tid; i < n; i += NTHR) {
                u64 v = s[i];
                if ((v & mask) == prefix) lm = min(lm, v);
            }
            #pragma unroll
            for (int o = 16; o > 0; o >>= 1)
                lm = min(lm, __shfl_down_sync(0xFFFFFFFFu, lm, o));
            if (lane == 0) atomicMin(&w->minkey, lm);
            __syncthreads();
            return w->minkey;
        }
        __syncthreads();
    }
    return prefix;
}

template <int NTHR>
__device__ void compact_ge(const u64* s, int n, u64 thr, u64* dst,
                           int* sh_cnt, int tid) {
    if (tid == 0) *sh_cnt = 0;
    __syncthreads();
    #pragma unroll 1
    for (int i = tid; i < n; i += NTHR) {
        u64 v = s[i];
        if (v >= thr) dst[atomicAdd(sh_cnt, 1)] = v;
    }
    __syncthreads();
}

template <int NSORT, int NTHREADS>
__device__ __forceinline__ void bitonic_desc(u64* s, int tid) {
    #pragma unroll 1
    for (int k = 2; k <= NSORT; k <<= 1) {
        #pragma unroll 1
        for (int j = k >> 1; j > 0; j >>= 1) {
            for (int i = tid; i < NSORT; i += NTHREADS) {
                int ixj = i ^ j;
                if (ixj > i) {
                    u64 a = s[i], b = s[ixj];
                    if ((a < b) == ((i & k) == 0)) { s[i] = b; s[ixj] = a; }
                }
            }
            __syncthreads();
        }
    }
}

// ---------------------------------------------------------------------------
// Fused kernel
// out layout (float32): scores[B*K] | labels[B*K] | boxes[B*K*4]
// ---------------------------------------------------------------------------
__global__ __launch_bounds__(T1, 2)
void postproc_kernel(const float* __restrict__ logits,
                     const float* __restrict__ bbox,
                     const float* __restrict__ tsz,
                     float* __restrict__ out) {
    __shared__ u64 buf[BUF];
    __shared__ u64 stage[KEEP];
    __shared__ SelWS ws;
    __shared__ int cnt;
    __shared__ u64 thr64_s;
    __shared__ float guard_s;
    __shared__ int merge_flag;

    const int b    = blockIdx.y;
    const int ch   = blockIdx.x;
    const int tid  = threadIdx.x;
    const int lane = tid & 31;

    const float4* __restrict__ base =
        reinterpret_cast<const float4*>(logits + (size_t)b * NTOT);

    const int per = (N4 + CHUNKS - 1) / CHUNKS;   // 75188
    const int lo  = ch * per;
    const int hi  = min(lo + per, N4);

    // ---- Phase A: tile 0 -> raw logit keys -> derive guard ----
    {
        #pragma unroll
        for (int j = 0; j < VPT; j++) {
            const int i = lo + j * T1 + tid;
            float4 v = (i < hi) ? __ldcs(base + i)
                                : make_float4(NEG_INF, NEG_INF, NEG_INF, NEG_INF);
            const int x0 = i * 4;
            buf[(j * 4 + 0) * T1 + tid] = packlogit(v.x, x0 + 0);
            buf[(j * 4 + 1) * T1 + tid] = packlogit(v.y, x0 + 1);
            buf[(j * 4 + 2) * T1 + tid] = packlogit(v.z, x0 + 2);
            buf[(j * 4 + 3) * T1 + tid] = packlogit(v.w, x0 + 3);
        }
        __syncthreads();
        u64 kth = radix_kth<T1>(buf, 4 * TILE_F4, KEEP, &ws, tid);
        if (tid == 0) {
            const float L = ord2f((unsigned)(kth >> 32));
            const float p = 1.0f / (1.0f + expf(-L));   // accurate sigmoid
            guard_s = guard_from_prob(p);
            thr64_s = 0ull;
            cnt = 0;
        }
        __syncthreads();
    }

    // ---- Phase B: software-pipelined guarded streaming pass ----
    float4 v[VPT];
    int    ix[VPT];
    #pragma unroll
    for (int j = 0; j < VPT; j++) {
        const int i = lo + j * T1 + tid;
        ix[j] = i;
        v[j] = (i < hi) ? __ldcs(base + i)
                        : make_float4(NEG_INF, NEG_INF, NEG_INF, NEG_INF);
    }

    #pragma unroll 1
    for (int t0 = lo; t0 < hi; t0 += TILE_F4) {
        // issue next tile's loads before touching this tile (hide latency
        // across the barrier below)
        float4 nv[VPT];
        int    nix[VPT];
        const int nt0 = t0 + TILE_F4;
        if (nt0 < hi) {
            #pragma unroll
            for (int j = 0; j < VPT; j++) {
                const int i = nt0 + j * T1 + tid;
                nix[j] = i;
                nv[j] = (i < hi) ? __ldcs(base + i)
                                 : make_float4(NEG_INF, NEG_INF, NEG_INF, NEG_INF);
            }
        }

        // per-thread local collect (predicated; expected <1 per thread)
        const float g = guard_s;
        float loc_f[16];
        int   loc_i[16];
        int   nl = 0;
        #pragma unroll
        for (int j = 0; j < VPT; j++) {
            const int x0 = ix[j] * 4;
            const float f0 = v[j].x, f1 = v[j].y, f2 = v[j].z, f3 = v[j].w;
            if (f0 > g) { loc_f[nl] = f0; loc_i[nl] = x0 + 0; nl++; }
            if (f1 > g) { loc_f[nl] = f1; loc_i[nl] = x0 + 1; nl++; }
            if (f2 > g) { loc_f[nl] = f2; loc_i[nl] = x0 + 2; nl++; }
            if (f3 > g) { loc_f[nl] = f3; loc_i[nl] = x0 + 3; nl++; }
        }
        // one aggregated append per warp per tile
        if (__ballot_sync(0xFFFFFFFFu, nl > 0)) {
            const u64 th = thr64_s;
            u64 keys[16];
            int nk = 0;
            for (int j = 0; j < nl; j++) {
                u64 k = packprob(ref_sigmoid(loc_f[j]), loc_i[j]);
                if (k > th) keys[nk++] = k;
            }
            int pre = nk;
            #pragma unroll
            for (int o = 1; o < 32; o <<= 1) {
                int u = __shfl_up_sync(0xFFFFFFFFu, pre, o);
                if (lane >= o) pre += u;
            }
            int tot = __shfl_sync(0xFFFFFFFFu, pre, 31);
            if (tot > 0) {
                int bpos = 0;
                if (lane == 31) bpos = atomicAdd(&cnt, tot);
                bpos = __shfl_sync(0xFFFFFFFFu, bpos, 31);
                const int p = bpos + pre - nk;
                for (int j = 0; j < nk; j++) buf[p + j] = keys[j];
            }
        }
        __syncthreads();

        if (cnt > WATERMARK) {                 // prune (~once per CTA)
            u64 kth = radix_kth<T1>(buf, cnt, KEEP, &ws, tid);
            compact_ge<T1>(buf, cnt, kth, stage, &ws.sh_cnt, tid);
            for (int p = tid; p < KEEP; p += T1) buf[p] = stage[p];
            if (tid == 0) {
                cnt     = KEEP;
                thr64_s = kth;
                guard_s = guard_from_prob(__uint_as_float((unsigned)(kth >> 32)));
            }
            __syncthreads();
        }

        #pragma unroll
        for (int j = 0; j < VPT; j++) { v[j] = nv[j]; ix[j] = nix[j]; }
    }

    // ---- final exact top-KEEP of this chunk -> g_cand (unsorted) ----
    {
        const int n = cnt;
        u64 kth = radix_kth<T1>(buf, n, KEEP, &ws, tid);
        compact_ge<T1>(buf, n, kth, stage, &ws.sh_cnt, tid);
        u64* dst = g_cand + ((size_t)b * CHUNKS + ch) * KEEP;
        for (int p = tid; p < KEEP; p += T1) dst[p] = stage[p];
    }

    // ---- last CTA of this batch performs the merge ----
    __threadfence();
    if (tid == 0) {
        int prev = atomicAdd(&g_done[b], 1);
        merge_flag = (prev == CHUNKS - 1);
        if (merge_flag) g_done[b] = 0;        // self-reset for graph replays
    }
    __syncthreads();
    if (!merge_flag) return;
    __threadfence();

    const u64* src = g_cand + (size_t)b * MN;
    for (int i = tid; i < MN; i += T1) buf[i] = src[i];
    __syncthreads();

    u64 kth = radix_kth<T1>(buf, MN, KTOP, &ws, tid);
    compact_ge<T1>(buf, MN, kth, stage, &ws.sh_cnt, tid);
    for (int i = KTOP + tid; i < KEEP; i += T1) stage[i] = 0ull;
    __syncthreads();

    bitonic_desc<KEEP, T1>(stage, tid);

    if (tid < KTOP) {
        const u64 cb = stage[tid];
        const float score = __uint_as_float((unsigned)(cb >> 32));
        const unsigned idx = ~(unsigned)cb;

        const int q   = (int)(idx / CN);
        const int lab = (int)(idx % CN);

        const float4 bx = reinterpret_cast<const float4*>(bbox)[b * QN + q];
        const float ih = tsz[b * 2 + 0];
        const float iw = tsz[b * 2 + 1];

        out[b * KTOP + tid] = score;                        // scores
        out[BATCH * KTOP + b * KTOP + tid] = (float)lab;    // labels
        float4 bo;
        bo.x = (bx.x - 0.5f * bx.z) * iw;
        bo.y = (bx.y - 0.5f * bx.w) * ih;
        bo.z = (bx.x + 0.5f * bx.z) * iw;
        bo.w = (bx.y + 0.5f * bx.w) * ih;
        reinterpret_cast<float4*>(out + 2 * BATCH * KTOP)[b * KTOP + tid] = bo;
    }
}

extern "C" void kernel_launch(void* const* d_in, const int* in_sizes, int n_in,
                              void* d_out, int out_size) {
    const float* logits = (const float*)d_in[0];   // (64,1000,1203) f32
    const float* bbox   = (const float*)d_in[1];   // (64,1000,4)    f32
    const float* tsz    = (const float*)d_in[2];   // (64,2)         f32
    float* out          = (float*)d_out;           // 38400 f32

    dim3 grid(CHUNKS, BATCH);
    postproc_kernel<<<grid, T1>>>(logits, bbox, tsz, out);
}

// round 8
// speedup vs baseline: 5.8329x; 1.3541x over previous
#include <cuda_runtime.h>
#include <cstdint>

#define BATCH   64
#define QN      1000
#define CN      1203
#define NTOT    (QN * CN)          // 1203000 per batch
#define N4      (NTOT / 4)         // 300750 float4 per batch
#define KTOP    100
#define KEEP    128                // survivors per chunk
#define CHUNKS  4
#define T1      512
#define VPT     4                  // float4 per thread per tile
#define TILE_F4 (VPT * T1)         // 2048 float4 = 8192 floats
#define BUF     12288              // 96KB shared candidate buffer
#define WATERMARK (BUF - 4 * TILE_F4)   // worst-case tile append still fits
#define MN      (CHUNKS * KEEP)    // 512 merge candidates per batch

#define NEG_INF (-__int_as_float(0x7F800000))

typedef unsigned long long u64;

__device__ u64 g_cand[BATCH * CHUNKS * KEEP];
__device__ int g_done[BATCH];      // zero-init; self-resetting per launch

// Reference sigmoid: XLA-GPU logistic -> 0.5 + 0.5*tanh.approx(0.5*x)
__device__ __forceinline__ float ref_sigmoid(float x) {
    float t;
    asm("tanh.approx.f32 %0, %1;" : "=f"(t) : "f"(x * 0.5f));
    return fmaf(0.5f, t, 0.5f);
}

__device__ __forceinline__ u64 packprob(float p, int idx) {
    return ((u64)__float_as_uint(p) << 32) | (unsigned)(~idx);
}
__device__ __forceinline__ u64 packlogit(float x, int idx) {
    unsigned bits = __float_as_uint(x);
    bits = (bits & 0x80000000u) ? ~bits : (bits | 0x80000000u);
    return ((u64)bits << 32) | (unsigned)(~idx);
}
__device__ __forceinline__ float ord2f(unsigned k) {
    unsigned x = (k & 0x80000000u) ? (k & 0x7FFFFFFFu) : ~k;
    return __uint_as_float(x);
}

// conservative logit guard: x <= guard => mufu_prob(x) < p (with margin)
__device__ __forceinline__ float guard_from_prob(float p) {
    float pf = p - 2e-3f;              // >= 3x mufu tanh abs-error bound
    if (pf <= 1e-7f) return NEG_INF;
    if (pf >= 1.0f - 1e-7f) pf = 1.0f - 1e-7f;
    return __logf(pf / (1.0f - pf)) - 2e-2f;
}

struct SelWS {
    int hist[256];
    int suff[257];
    int wsum[8];
    u64 sh_pref;
    u64 minkey;
    int sh_k;
    int flag;
    int sh_cnt;
};

// exact k-th largest u64 among s[0..n): MSD radix descent with
// match-aggregated histograms and early exit.
template <int NTHR>
__device__ u64 radix_kth(const u64* s, int n, int k, SelWS* w, int tid) {
    const int lane = tid & 31;
    u64 prefix = 0, mask = 0;
    int kk = k;
    #pragma unroll 1
    for (int shift = 56; shift >= 0; shift -= 8) {
        if (tid < 256) w->hist[tid] = 0;
        if (tid == 0) w->flag = 0;
        __syncthreads();
        #pragma unroll 1
        for (int i = tid; (i - lane) < n; i += NTHR) {
            u64 v = (i < n) ? s[i] : 0ull;
            bool act = (i < n) && ((v & mask) == prefix);
            unsigned grp = __ballot_sync(0xFFFFFFFFu, act);
            if (act) {
                int d = (int)((v >> shift) & 255);
                unsigned peers = __match_any_sync(grp, d);
                if (lane == __ffs(peers) - 1)
                    atomicAdd(&w->hist[d], __popc(peers));
            }
        }
        __syncthreads();
        int ss = 0;
        if (tid < 256) {
            ss = w->hist[tid];
            #pragma unroll
            for (int o = 1; o < 32; o <<= 1) {
                int u = __shfl_down_sync(0xFFFFFFFFu, ss, o);
                if (lane + o < 32) ss += u;
            }
            if (lane == 0) w->wsum[tid >> 5] = ss;
        }
        __syncthreads();
        if (tid == 0) {
            int acc = 0;
            #pragma unroll
            for (int wi = 7; wi >= 0; --wi) { int t = w->wsum[wi]; w->wsum[wi] = acc; acc += t; }
            w->suff[256] = 0;
        }
        __syncthreads();
        if (tid < 256) w->suff[tid] = ss + w->wsum[tid >> 5];
        __syncthreads();
        if (tid < 256) {
            int GE = w->suff[tid], GT = w->suff[tid + 1];
            if (GT < kk && kk <= GE) {
                w->sh_k = kk - GT;
                w->sh_pref = prefix | ((u64)tid << shift);
                w->flag = ((kk - GT) == (GE - GT)) ? 1 : 0;
            }
        }
        __syncthreads();
        prefix = w->sh_pref;
        kk = w->sh_k;
        mask |= (0xFFull << shift);
        if (w->flag || shift == 0) {
            if (tid == 0) w->minkey = ~0ull;
            __syncthreads();
            u64 lm = ~0ull;
            #pragma unroll 1
            for (int i = tid; i < n; i += NTHR) {
                u64 v = s[i];
                if ((v & mask) == prefix) lm = min(lm, v);
            }
            #pragma unroll
            for (int o = 16; o > 0; o >>= 1)
                lm = min(lm, __shfl_down_sync(0xFFFFFFFFu, lm, o));
            if (lane == 0) atomicMin(&w->minkey, lm);
            __syncthreads();
            return w->minkey;
        }
        __syncthreads();
    }
    return prefix;
}

template <int NTHR>
__device__ void compact_ge(const u64* s, int n, u64 thr, u64* dst,
                           int* sh_cnt, int tid) {
    if (tid == 0) *sh_cnt = 0;
    __syncthreads();
    #pragma unroll 1
    for (int i = tid; i < n; i += NTHR) {
        u64 v = s[i];
        if (v >= thr) dst[atomicAdd(sh_cnt, 1)] = v;
    }
    __syncthreads();
}

template <int NSORT, int NTHREADS>
__device__ __forceinline__ void bitonic_desc(u64* s, int tid) {
    #pragma unroll 1
    for (int k = 2; k <= NSORT; k <<= 1) {
        #pragma unroll 1
        for (int j = k >> 1; j > 0; j >>= 1) {
            for (int i = tid; i < NSORT; i += NTHREADS) {
                int ixj = i ^ j;
                if (ixj > i) {
                    u64 a = s[i], b = s[ixj];
                    if ((a < b) == ((i & k) == 0)) { s[i] = b; s[ixj] = a; }
                }
            }
            __syncthreads();
        }
    }
}

__device__ __forceinline__ float elem_of(const float4* v, int e) {
    // e is a compile-time constant at each unrolled call site
    const float4 q = v[e >> 2];
    switch (e & 3) {
        case 0: return q.x;
        case 1: return q.y;
        case 2: return q.z;
        default: return q.w;
    }
}

// ---------------------------------------------------------------------------
// Fused kernel
// out layout (float32): scores[B*K] | labels[B*K] | boxes[B*K*4]
// ---------------------------------------------------------------------------
__global__ __launch_bounds__(T1, 2)
void postproc_kernel(const float* __restrict__ logits,
                     const float* __restrict__ bbox,
                     const float* __restrict__ tsz,
                     float* __restrict__ out) {
    __shared__ u64 buf[BUF];
    __shared__ u64 stage[KEEP];
    __shared__ SelWS ws;
    __shared__ int cnt;
    __shared__ float guard_s;
    __shared__ int merge_flag;

    const int b    = blockIdx.y;
    const int ch   = blockIdx.x;
    const int tid  = threadIdx.x;
    const int lane = tid & 31;

    const float4* __restrict__ base =
        reinterpret_cast<const float4*>(logits + (size_t)b * NTOT);

    const int per = (N4 + CHUNKS - 1) / CHUNKS;   // 75188
    const int lo  = ch * per;
    const int hi  = min(lo + per, N4);

    // ---- Phase A: tile 0 -> raw logit keys -> derive guard ----
    {
        #pragma unroll
        for (int j = 0; j < VPT; j++) {
            const int i = lo + j * T1 + tid;
            float4 v = (i < hi) ? __ldcs(base + i)
                                : make_float4(NEG_INF, NEG_INF, NEG_INF, NEG_INF);
            const int x0 = i * 4;
            buf[(j * 4 + 0) * T1 + tid] = packlogit(v.x, x0 + 0);
            buf[(j * 4 + 1) * T1 + tid] = packlogit(v.y, x0 + 1);
            buf[(j * 4 + 2) * T1 + tid] = packlogit(v.z, x0 + 2);
            buf[(j * 4 + 3) * T1 + tid] = packlogit(v.w, x0 + 3);
        }
        __syncthreads();
        u64 kth = radix_kth<T1>(buf, 4 * TILE_F4, KEEP, &ws, tid);
        if (tid == 0) {
            const float L = ord2f((unsigned)(kth >> 32));
            const float p = 1.0f / (1.0f + expf(-L));   // accurate sigmoid
            guard_s = guard_from_prob(p);
            cnt = 0;
        }
        __syncthreads();
    }

    // ---- Phase B: pipelined, spill-free guarded streaming pass ----
    float4 v[VPT];
    #pragma unroll
    for (int j = 0; j < VPT; j++) {
        const int i = lo + j * T1 + tid;
        v[j] = (i < hi) ? __ldcs(base + i)
                        : make_float4(NEG_INF, NEG_INF, NEG_INF, NEG_INF);
    }

    #pragma unroll 1
    for (int t0 = lo; t0 < hi; t0 += TILE_F4) {
        // prefetch next tile into registers before processing this one
        float4 nv[VPT];
        const int nt0 = t0 + TILE_F4;
        #pragma unroll
        for (int j = 0; j < VPT; j++) {
            const int i = nt0 + j * T1 + tid;
            nv[j] = (i < hi) ? __ldcs(base + i)
                             : make_float4(NEG_INF, NEG_INF, NEG_INF, NEG_INF);
        }

        // 16 predicated compares -> one mask register (no local arrays)
        const float g = guard_s;
        unsigned m = 0;
        #pragma unroll
        for (int e = 0; e < 16; e++)
            if (elem_of(v, e) > g) m |= (1u << e);

        if (__ballot_sync(0xFFFFFFFFu, m != 0)) {
            int nk = __popc(m);
            int pre = nk;
            #pragma unroll
            for (int o = 1; o < 32; o <<= 1) {
                int u = __shfl_up_sync(0xFFFFFFFFu, pre, o);
                if (lane >= o) pre += u;
            }
            int tot = __shfl_sync(0xFFFFFFFFu, pre, 31);
            int bpos = 0;
            if (lane == 31 && tot > 0) bpos = atomicAdd(&cnt, tot);
            bpos = __shfl_sync(0xFFFFFFFFu, bpos, 31);
            int pos = bpos + pre - nk;
            #pragma unroll
            for (int e = 0; e < 16; e++) {
                if (m & (1u << e)) {
                    const float f = elem_of(v, e);
                    const int idx = (t0 + (e >> 2) * T1 + tid) * 4 + (e & 3);
                    buf[pos++] = packprob(ref_sigmoid(f), idx);
                }
            }
        }
        __syncthreads();

        if (cnt > WATERMARK) {                 // prune (~once per CTA)
            u64 kth = radix_kth<T1>(buf, cnt, KEEP, &ws, tid);
            compact_ge<T1>(buf, cnt, kth, stage, &ws.sh_cnt, tid);
            for (int p = tid; p < KEEP; p += T1) buf[p] = stage[p];
            if (tid == 0) {
                cnt     = KEEP;
                guard_s = guard_from_prob(__uint_as_float((unsigned)(kth >> 32)));
            }
            __syncthreads();
        }

        #pragma unroll
        for (int j = 0; j < VPT; j++) v[j] = nv[j];
    }

    // ---- final exact top-KEEP of this chunk -> g_cand (unsorted) ----
    {
        const int n = cnt;
        u64 kth = radix_kth<T1>(buf, n, KEEP, &ws, tid);
        compact_ge<T1>(buf, n, kth, stage, &ws.sh_cnt, tid);
        u64* dst = g_cand + ((size_t)b * CHUNKS + ch) * KEEP;
        for (int p = tid; p < KEEP; p += T1) dst[p] = stage[p];
    }

    // ---- last CTA of this batch performs the merge ----
    __threadfence();
    if (tid == 0) {
        int prev = atomicAdd(&g_done[b], 1);
        merge_flag = (prev == CHUNKS - 1);
        if (merge_flag) g_done[b] = 0;        // self-reset for graph replays
    }
    __syncthreads();
    if (!merge_flag) return;
    __threadfence();

    const u64* src = g_cand + (size_t)b * MN;
    for (int i = tid; i < MN; i += T1) buf[i] = src[i];
    __syncthreads();

    u64 kth = radix_kth<T1>(buf, MN, KTOP, &ws, tid);
    compact_ge<T1>(buf, MN, kth, stage, &ws.sh_cnt, tid);
    for (int i = KTOP + tid; i < KEEP; i += T1) stage[i] = 0ull;
    __syncthreads();

    bitonic_desc<KEEP, T1>(stage, tid);

    if (tid < KTOP) {
        const u64 cb = stage[tid];
        const float score = __uint_as_float((unsigned)(cb >> 32));
        const unsigned idx = ~(unsigned)cb;

        const int q   = (int)(idx / CN);
        const int lab = (int)(idx % CN);

        const float4 bx = reinterpret_cast<const float4*>(bbox)[b * QN + q];
        const float ih = tsz[b * 2 + 0];
        const float iw = tsz[b * 2 + 1];

        out[b * KTOP + tid] = score;                        // scores
        out[BATCH * KTOP + b * KTOP + tid] = (float)lab;    // labels
        float4 bo;
        bo.x = (bx.x - 0.5f * bx.z) * iw;
        bo.y = (bx.y - 0.5f * bx.w) * ih;
        bo.z = (bx.x + 0.5f * bx.z) * iw;
        bo.w = (bx.y + 0.5f * bx.w) * ih;
        reinterpret_cast<float4*>(out + 2 * BATCH * KTOP)[b * KTOP + tid] = bo;
    }
}

extern "C" void kernel_launch(void* const* d_in, const int* in_sizes, int n_in,
                              void* d_out, int out_size) {
    const float* logits = (const float*)d_in[0];   // (64,1000,1203) f32
    const float* bbox   = (const float*)d_in[1];   // (64,1000,4)    f32
    const float* tsz    = (const float*)d_in[2];   // (64,2)         f32
    float* out          = (float*)d_out;           // 38400 f32

    dim3 grid(CHUNKS, BATCH);
    postproc_kernel<<<grid, T1>>>(logits, bbox, tsz, out);
}